// round 2
// baseline (speedup 1.0000x reference)
#include <cuda_runtime.h>

#define B_  512
#define T_  1024
#define IN_ 128
#define H_  64
#define NG_ 256
#define BT_ (B_ * T_)

// xg scratch: [dir][b*T+t][hh*4+gate]  (1 GiB)
__device__ float g_G[(size_t)2 * BT_ * NG_];

// ---------------- f32x2 helpers (Blackwell packed fp32) ----------------
__device__ __forceinline__ unsigned long long ffma2(unsigned long long a,
                                                    unsigned long long b,
                                                    unsigned long long c) {
    unsigned long long d;
    asm("fma.rn.f32x2 %0, %1, %2, %3;" : "=l"(d) : "l"(a), "l"(b), "l"(c));
    return d;
}
__device__ __forceinline__ unsigned long long splat2(float x) {
    unsigned long long d;
    unsigned int u = __float_as_uint(x);
    asm("mov.b64 %0, {%1, %1};" : "=l"(d) : "r"(u));
    return d;
}
__device__ __forceinline__ void unpack2(unsigned long long v, float& lo, float& hi) {
    unsigned int a, b;
    asm("mov.b64 {%0, %1}, %2;" : "=r"(a), "=r"(b) : "l"(v));
    lo = __uint_as_float(a);
    hi = __uint_as_float(b);
}

// ---------------- activations ----------------
__device__ __forceinline__ float sigf(float x) {
    return __fdividef(1.f, 1.f + __expf(-x));
}
__device__ __forceinline__ float tanhf_(float x) {
    x = fminf(fmaxf(x, -15.f), 15.f);
    float e = __expf(-2.f * x);
    return __fdividef(1.f - e, 1.f + e);
}

// =======================================================================
// Kernel 1: xg[dir][m][p] = sum_i x[m][i] * Wih[dir][j][i] + b[dir][j]
// where m = b*T + t, j = gate*64 + hh, stored at p = hh*4 + gate.
// CTA tile: 128 m-rows x 256 cols (one dir). 256 threads, 8m x 8 n-pairs
// per thread, all FFMA2.
// =======================================================================
__global__ void __launch_bounds__(256, 1) gates_gemm(
    const float* __restrict__ x,
    const float* __restrict__ Wf, const float* __restrict__ bf,
    const float* __restrict__ Wb, const float* __restrict__ bb)
{
    extern __shared__ float sm[];
    float* W_s = sm;                  // [128][256], col index is permuted p
    float* x_s = sm + 128 * 256;      // [128][129] padded
    float* b_s = x_s + 128 * 129;     // [256] permuted

    const int tid   = threadIdx.x;
    const int dir   = blockIdx.x & 1;
    const int mtile = blockIdx.x >> 1;
    const size_t m0 = (size_t)mtile * 128;

    const float* W    = dir ? Wb : Wf;
    const float* bias = dir ? bb : bf;

    // load Wih permuted: W_s[i][p(j)]
    {
        const int j = tid;
        const int p = ((j & 63) << 2) | (j >> 6);
        const float4* wr = (const float4*)(W + j * IN_);
#pragma unroll
        for (int iq = 0; iq < 32; iq++) {
            float4 v = wr[iq];
            W_s[(iq * 4 + 0) * 256 + p] = v.x;
            W_s[(iq * 4 + 1) * 256 + p] = v.y;
            W_s[(iq * 4 + 2) * 256 + p] = v.z;
            W_s[(iq * 4 + 3) * 256 + p] = v.w;
        }
        b_s[p] = bias[j];
    }
    // load x tile [128 rows][128 k]
    for (int idx = tid; idx < 128 * 32; idx += 256) {
        const int m = idx >> 5, iq = idx & 31;
        float4 v = *(const float4*)(x + (m0 + m) * IN_ + iq * 4);
        x_s[m * 129 + iq * 4 + 0] = v.x;
        x_s[m * 129 + iq * 4 + 1] = v.y;
        x_s[m * 129 + iq * 4 + 2] = v.z;
        x_s[m * 129 + iq * 4 + 3] = v.w;
    }
    __syncthreads();

    const int mg = tid & 15;   // 16 groups x 8 m
    const int ng = tid >> 4;   // 16 groups x 16 p

    unsigned long long acc[8][8];
#pragma unroll
    for (int r = 0; r < 8; r++)
#pragma unroll
        for (int c = 0; c < 8; c++) acc[r][c] = 0ULL;

    const float* xrow = x_s + mg * 8 * 129;
    const float* wcol = W_s + ng * 16;

#pragma unroll 4
    for (int k = 0; k < 128; k++) {
        ulonglong2 wA = *(const ulonglong2*)(wcol + k * 256);
        ulonglong2 wB = *(const ulonglong2*)(wcol + k * 256 + 4);
        ulonglong2 wC = *(const ulonglong2*)(wcol + k * 256 + 8);
        ulonglong2 wD = *(const ulonglong2*)(wcol + k * 256 + 12);
#pragma unroll
        for (int r = 0; r < 8; r++) {
            unsigned long long a = splat2(xrow[r * 129 + k]);
            acc[r][0] = ffma2(a, wA.x, acc[r][0]);
            acc[r][1] = ffma2(a, wA.y, acc[r][1]);
            acc[r][2] = ffma2(a, wB.x, acc[r][2]);
            acc[r][3] = ffma2(a, wB.y, acc[r][3]);
            acc[r][4] = ffma2(a, wC.x, acc[r][4]);
            acc[r][5] = ffma2(a, wC.y, acc[r][5]);
            acc[r][6] = ffma2(a, wD.x, acc[r][6]);
            acc[r][7] = ffma2(a, wD.y, acc[r][7]);
        }
    }

    // epilogue: add bias, store
#pragma unroll
    for (int r = 0; r < 8; r++) {
        const size_t mrow = m0 + mg * 8 + r;
        float* orow = g_G + ((size_t)dir * BT_ + mrow) * NG_ + ng * 16;
#pragma unroll
        for (int c4 = 0; c4 < 4; c4++) {
            float f0, f1, f2, f3;
            unpack2(acc[r][c4 * 2 + 0], f0, f1);
            unpack2(acc[r][c4 * 2 + 1], f2, f3);
            f0 += b_s[ng * 16 + c4 * 4 + 0];
            f1 += b_s[ng * 16 + c4 * 4 + 1];
            f2 += b_s[ng * 16 + c4 * 4 + 2];
            f3 += b_s[ng * 16 + c4 * 4 + 3];
            float4 v = make_float4(f0, f1, f2, f3);
            *(float4*)(orow + c4 * 4) = v;
        }
    }
}

// =======================================================================
// Kernel 2: recurrence. 128 CTAs = (2 dirs) x (64 batch-chunks of 8).
// 256 threads: thread = gate row j (Whh[j][:] register-resident).
// h[8 batches][64] in smem; b-pairs packed for FFMA2.
// Epilogue: thread handles 2 (b,hh) units; c state in regs.
// =======================================================================
__global__ void __launch_bounds__(256, 1) lstm_rec(
    const float* __restrict__ Whh_f, const float* __restrict__ Whh_b,
    float* __restrict__ out)
{
    __shared__ __align__(16) float h_s[64][8];   // [k][b]
    __shared__ __align__(16) float gq[8][256];   // [b][hh*4+gate]

    const int tid = threadIdx.x;
    const int dir = blockIdx.x >> 6;
    const int b0  = (blockIdx.x & 63) << 3;

    const float* Whh = dir ? Whh_b : Whh_f;

    float w[64];
#pragma unroll
    for (int k = 0; k < 64; k++) w[k] = Whh[tid * 64 + k];

    const int gate = tid >> 6;
    const int hh   = tid & 63;
    const int pj   = (hh << 2) | gate;

    const int b_act = tid >> 5;          // 0..7
    const int hh2   = (tid & 31) << 1;   // 0,2,..,62

    ((float*)h_s)[tid]       = 0.f;
    ((float*)h_s)[tid + 256] = 0.f;
    float c0 = 0.f, c1 = 0.f;
    __syncthreads();

    const size_t xg_base =
        ((size_t)dir * BT_ + (size_t)(b0 + b_act) * T_) * NG_ + (size_t)(hh2 << 2);
    float* out_base = out + (size_t)(b0 + b_act) * T_ * 128 + dir * 64 + hh2;

    for (int s = 0; s < T_; s++) {
        const int t = dir ? (T_ - 1 - s) : s;

        // prefetch xg for this step (consumed after the K-loop + barrier)
        const float* gp = g_G + xg_base + (size_t)t * NG_;
        float4 xa = *(const float4*)gp;
        float4 xb = *(const float4*)(gp + 4);

        // recurrent matvec: g[b][j] = sum_k h[b][k] * w[k]
        unsigned long long a0 = 0, a1 = 0, a2 = 0, a3 = 0;
#pragma unroll
        for (int k = 0; k < 64; k++) {
            ulonglong2 h01 = *(const ulonglong2*)&h_s[k][0];
            ulonglong2 h23 = *(const ulonglong2*)&h_s[k][4];
            unsigned long long wv = splat2(w[k]);
            a0 = ffma2(h01.x, wv, a0);
            a1 = ffma2(h01.y, wv, a1);
            a2 = ffma2(h23.x, wv, a2);
            a3 = ffma2(h23.y, wv, a3);
        }
        float g0, g1, g2, g3, g4, g5, g6, g7;
        unpack2(a0, g0, g1);
        unpack2(a1, g2, g3);
        unpack2(a2, g4, g5);
        unpack2(a3, g6, g7);
        gq[0][pj] = g0; gq[1][pj] = g1; gq[2][pj] = g2; gq[3][pj] = g3;
        gq[4][pj] = g4; gq[5][pj] = g5; gq[6][pj] = g6; gq[7][pj] = g7;
        __syncthreads();

        float4 ga = *(const float4*)&gq[b_act][hh2 << 2];
        float4 gb = *(const float4*)&gq[b_act][(hh2 << 2) + 4];

        float i0 = ga.x + xa.x, f0v = ga.y + xa.y, gg0 = ga.z + xa.z, o0 = ga.w + xa.w;
        c0 = sigf(f0v) * c0 + sigf(i0) * tanhf_(gg0);
        float h0 = sigf(o0) * tanhf_(c0);

        float i1 = gb.x + xb.x, f1v = gb.y + xb.y, gg1 = gb.z + xb.z, o1 = gb.w + xb.w;
        c1 = sigf(f1v) * c1 + sigf(i1) * tanhf_(gg1);
        float h1 = sigf(o1) * tanhf_(c1);

        h_s[hh2][b_act]     = h0;
        h_s[hh2 + 1][b_act] = h1;
        float2 hv = make_float2(h0, h1);
        *(float2*)(out_base + (size_t)t * 128) = hv;
        __syncthreads();
    }
}

// =======================================================================
extern "C" void kernel_launch(void* const* d_in, const int* in_sizes, int n_in,
                              void* d_out, int out_size)
{
    const float* x    = (const float*)d_in[0];
    const float* Wihf = (const float*)d_in[1];
    const float* Whhf = (const float*)d_in[2];
    const float* bf   = (const float*)d_in[3];
    const float* Wihb = (const float*)d_in[4];
    const float* Whhb = (const float*)d_in[5];
    const float* bb   = (const float*)d_in[6];
    float* out = (float*)d_out;

    const int smem = (128 * 256 + 128 * 129 + 256) * 4;  // 198144 B
    cudaFuncSetAttribute(gates_gemm, cudaFuncAttributeMaxDynamicSharedMemorySize, smem);

    gates_gemm<<<(BT_ / 128) * 2, 256, smem>>>(x, Wihf, bf, Wihb, bb);
    lstm_rec<<<128, 256>>>(Whhf, Whhb, out);
}

// round 3
// speedup vs baseline: 1.0719x; 1.0719x over previous
#include <cuda_runtime.h>

#define B_  512
#define T_  1024
#define IN_ 128
#define H_  64
#define NG_ 256
#define BT_ (B_ * T_)

// xg scratch: [dir][b*T+t][hh*4+gate]  (1 GiB)
__device__ float g_G[(size_t)2 * BT_ * NG_];

// ---------------- f32x2 helpers (Blackwell packed fp32) ----------------
__device__ __forceinline__ unsigned long long ffma2(unsigned long long a,
                                                    unsigned long long b,
                                                    unsigned long long c) {
    unsigned long long d;
    asm("fma.rn.f32x2 %0, %1, %2, %3;" : "=l"(d) : "l"(a), "l"(b), "l"(c));
    return d;
}
__device__ __forceinline__ unsigned long long splat2(float x) {
    unsigned long long d;
    unsigned int u = __float_as_uint(x);
    asm("mov.b64 %0, {%1, %1};" : "=l"(d) : "r"(u));
    return d;
}
__device__ __forceinline__ void unpack2(unsigned long long v, float& lo, float& hi) {
    unsigned int a, b;
    asm("mov.b64 {%0, %1}, %2;" : "=r"(a), "=r"(b) : "l"(v));
    lo = __uint_as_float(a);
    hi = __uint_as_float(b);
}

// ---------------- activations (MUFU tanh) ----------------
__device__ __forceinline__ float tanh_fast(float x) {
    float y;
    asm("tanh.approx.f32 %0, %1;" : "=f"(y) : "f"(x));
    return y;
}
__device__ __forceinline__ float sig_fast(float x) {
    return fmaf(tanh_fast(0.5f * x), 0.5f, 0.5f);
}

// =======================================================================
// Kernel 1: xg[dir][m][p] = sum_i x[m][i] * Wih[dir][j][i] + b[dir][j]
// where m = b*T + t, j = gate*64 + hh, stored at p = hh*4 + gate.
// CTA tile: 128 m-rows x 256 cols (one dir). 256 threads, 8m x 8 n-pairs
// per thread, all FFMA2.
// =======================================================================
__global__ void __launch_bounds__(256, 1) gates_gemm(
    const float* __restrict__ x,
    const float* __restrict__ Wf, const float* __restrict__ bf,
    const float* __restrict__ Wb, const float* __restrict__ bb)
{
    extern __shared__ float sm[];
    float* W_s = sm;                  // [128][256], col index is permuted p
    float* x_s = sm + 128 * 256;      // [128][129] padded
    float* b_s = x_s + 128 * 129;     // [256] permuted

    const int tid   = threadIdx.x;
    const int dir   = blockIdx.x & 1;
    const int mtile = blockIdx.x >> 1;
    const size_t m0 = (size_t)mtile * 128;

    const float* W    = dir ? Wb : Wf;
    const float* bias = dir ? bb : bf;

    // load Wih permuted: W_s[i][p(j)]
    {
        const int j = tid;
        const int p = ((j & 63) << 2) | (j >> 6);
        const float4* wr = (const float4*)(W + j * IN_);
#pragma unroll
        for (int iq = 0; iq < 32; iq++) {
            float4 v = wr[iq];
            W_s[(iq * 4 + 0) * 256 + p] = v.x;
            W_s[(iq * 4 + 1) * 256 + p] = v.y;
            W_s[(iq * 4 + 2) * 256 + p] = v.z;
            W_s[(iq * 4 + 3) * 256 + p] = v.w;
        }
        b_s[p] = bias[j];
    }
    // load x tile [128 rows][128 k]
    for (int idx = tid; idx < 128 * 32; idx += 256) {
        const int m = idx >> 5, iq = idx & 31;
        float4 v = *(const float4*)(x + (m0 + m) * IN_ + iq * 4);
        x_s[m * 129 + iq * 4 + 0] = v.x;
        x_s[m * 129 + iq * 4 + 1] = v.y;
        x_s[m * 129 + iq * 4 + 2] = v.z;
        x_s[m * 129 + iq * 4 + 3] = v.w;
    }
    __syncthreads();

    const int mg = tid & 15;   // 16 groups x 8 m
    const int ng = tid >> 4;   // 16 groups x 16 p

    unsigned long long acc[8][8];
#pragma unroll
    for (int r = 0; r < 8; r++)
#pragma unroll
        for (int c = 0; c < 8; c++) acc[r][c] = 0ULL;

    const float* xrow = x_s + mg * 8 * 129;
    const float* wcol = W_s + ng * 16;

#pragma unroll 4
    for (int k = 0; k < 128; k++) {
        ulonglong2 wA = *(const ulonglong2*)(wcol + k * 256);
        ulonglong2 wB = *(const ulonglong2*)(wcol + k * 256 + 4);
        ulonglong2 wC = *(const ulonglong2*)(wcol + k * 256 + 8);
        ulonglong2 wD = *(const ulonglong2*)(wcol + k * 256 + 12);
#pragma unroll
        for (int r = 0; r < 8; r++) {
            unsigned long long a = splat2(xrow[r * 129 + k]);
            acc[r][0] = ffma2(a, wA.x, acc[r][0]);
            acc[r][1] = ffma2(a, wA.y, acc[r][1]);
            acc[r][2] = ffma2(a, wB.x, acc[r][2]);
            acc[r][3] = ffma2(a, wB.y, acc[r][3]);
            acc[r][4] = ffma2(a, wC.x, acc[r][4]);
            acc[r][5] = ffma2(a, wC.y, acc[r][5]);
            acc[r][6] = ffma2(a, wD.x, acc[r][6]);
            acc[r][7] = ffma2(a, wD.y, acc[r][7]);
        }
    }

    // epilogue: add bias, store
#pragma unroll
    for (int r = 0; r < 8; r++) {
        const size_t mrow = m0 + mg * 8 + r;
        float* orow = g_G + ((size_t)dir * BT_ + mrow) * NG_ + ng * 16;
#pragma unroll
        for (int c4 = 0; c4 < 4; c4++) {
            float f0, f1, f2, f3;
            unpack2(acc[r][c4 * 2 + 0], f0, f1);
            unpack2(acc[r][c4 * 2 + 1], f2, f3);
            f0 += b_s[ng * 16 + c4 * 4 + 0];
            f1 += b_s[ng * 16 + c4 * 4 + 1];
            f2 += b_s[ng * 16 + c4 * 4 + 2];
            f3 += b_s[ng * 16 + c4 * 4 + 3];
            float4 v = make_float4(f0, f1, f2, f3);
            *(float4*)(orow + c4 * 4) = v;
        }
    }
}

// =======================================================================
// Kernel 2: recurrence. 128 CTAs = (2 dirs) x (64 batch-chunks of 8).
// 512 threads (16 warps = 4/SMSP for latency hiding).
//   Matvec role:  thread = (j = tid&255, half = tid>>8).
//       Whh[j][:] register-resident; accumulates 4 batches (2 x f32x2).
//   Epilogue role: thread = (b_e = tid>>6, hh_e = tid&63) -> 1 h-unit,
//       5 MUFU tanh.approx, c-state in a register.
// =======================================================================
__global__ void __launch_bounds__(512, 1) lstm_rec(
    const float* __restrict__ Whh_f, const float* __restrict__ Whh_b,
    float* __restrict__ out)
{
    __shared__ __align__(16) float h_s[64][12];  // [k][b], padded row 48B
    __shared__ __align__(16) float gq[8][256];   // [b][hh*4+gate]

    const int tid = threadIdx.x;
    const int dir = blockIdx.x >> 6;
    const int b0  = (blockIdx.x & 63) << 3;

    const float* Whh = dir ? Whh_b : Whh_f;

    // matvec role
    const int j    = tid & 255;
    const int half = tid >> 8;           // 0: batches 0-3, 1: batches 4-7
    const int pj   = ((j & 63) << 2) | (j >> 6);

    float w[64];
#pragma unroll
    for (int k = 0; k < 64; k++) w[k] = Whh[j * 64 + k];

    // epilogue role
    const int b_e  = tid >> 6;           // 0..7
    const int hh_e = tid & 63;           // 0..63

    // init
    for (int idx = tid; idx < 64 * 12; idx += 512) ((float*)h_s)[idx] = 0.f;
    float c = 0.f;
    __syncthreads();

    const size_t xg_base =
        ((size_t)dir * BT_ + (size_t)(b0 + b_e) * T_) * NG_ + (size_t)(hh_e << 2);
    float* out_base = out + (size_t)(b0 + b_e) * T_ * 128 + dir * 64 + hh_e;

    for (int s = 0; s < T_; s++) {
        const int t = dir ? (T_ - 1 - s) : s;

        // prefetch xg for this step's epilogue (hidden behind the matvec)
        float4 xa = *(const float4*)(g_G + xg_base + (size_t)t * NG_);

        // recurrent matvec: g[b][j] = sum_k h[b][k] * w[k], 4 batches packed
        unsigned long long a0 = 0, a1 = 0;
#pragma unroll
        for (int k = 0; k < 64; k++) {
            ulonglong2 hv = *(const ulonglong2*)&h_s[k][half << 2];
            unsigned long long wv = splat2(w[k]);
            a0 = ffma2(hv.x, wv, a0);
            a1 = ffma2(hv.y, wv, a1);
        }
        {
            float g0, g1, g2, g3;
            unpack2(a0, g0, g1);
            unpack2(a1, g2, g3);
            const int bb = half << 2;
            gq[bb + 0][pj] = g0;
            gq[bb + 1][pj] = g1;
            gq[bb + 2][pj] = g2;
            gq[bb + 3][pj] = g3;
        }
        __syncthreads();

        // activation: one (b_e, hh_e) unit per thread
        float4 ga = *(const float4*)&gq[b_e][hh_e << 2];
        float gi = ga.x + xa.x;
        float gf = ga.y + xa.y;
        float gg = ga.z + xa.z;
        float go = ga.w + xa.w;

        c = sig_fast(gf) * c + sig_fast(gi) * tanh_fast(gg);
        float h = sig_fast(go) * tanh_fast(c);

        h_s[hh_e][b_e] = h;
        out_base[(size_t)t * 128] = h;
        __syncthreads();
    }
}

// =======================================================================
extern "C" void kernel_launch(void* const* d_in, const int* in_sizes, int n_in,
                              void* d_out, int out_size)
{
    const float* x    = (const float*)d_in[0];
    const float* Wihf = (const float*)d_in[1];
    const float* Whhf = (const float*)d_in[2];
    const float* bf   = (const float*)d_in[3];
    const float* Wihb = (const float*)d_in[4];
    const float* Whhb = (const float*)d_in[5];
    const float* bb   = (const float*)d_in[6];
    float* out = (float*)d_out;

    const int smem = (128 * 256 + 128 * 129 + 256) * 4;  // 198144 B
    cudaFuncSetAttribute(gates_gemm, cudaFuncAttributeMaxDynamicSharedMemorySize, smem);

    gates_gemm<<<(BT_ / 128) * 2, 256, smem>>>(x, Wihf, bf, Wihb, bb);
    lstm_rec<<<128, 512>>>(Whhf, Whhb, out);
}

// round 4
// speedup vs baseline: 1.1630x; 1.0850x over previous
#include <cuda_runtime.h>

#define B_  512
#define T_  1024
#define IN_ 128
#define H_  64
#define NG_ 256
#define BT_ (B_ * T_)

// xg scratch: [dir][b*T+t][hh*4+gate]  (1 GiB)
__device__ float g_G[(size_t)2 * BT_ * NG_];

// ---------------- f32x2 helpers (Blackwell packed fp32) ----------------
__device__ __forceinline__ unsigned long long ffma2(unsigned long long a,
                                                    unsigned long long b,
                                                    unsigned long long c) {
    unsigned long long d;
    asm("fma.rn.f32x2 %0, %1, %2, %3;" : "=l"(d) : "l"(a), "l"(b), "l"(c));
    return d;
}
__device__ __forceinline__ unsigned long long splat2(float x) {
    unsigned long long d;
    unsigned int u = __float_as_uint(x);
    asm("mov.b64 %0, {%1, %1};" : "=l"(d) : "r"(u));
    return d;
}
__device__ __forceinline__ void unpack2(unsigned long long v, float& lo, float& hi) {
    unsigned int a, b;
    asm("mov.b64 {%0, %1}, %2;" : "=r"(a), "=r"(b) : "l"(v));
    lo = __uint_as_float(a);
    hi = __uint_as_float(b);
}

// ---------------- activations (MUFU tanh) ----------------
__device__ __forceinline__ float tanh_fast(float x) {
    float y;
    asm("tanh.approx.f32 %0, %1;" : "=f"(y) : "f"(x));
    return y;
}
__device__ __forceinline__ float sig_fast(float x) {
    return fmaf(tanh_fast(0.5f * x), 0.5f, 0.5f);
}

// =======================================================================
// Kernel 1 (persistent): xg[dir][m][p] = sum_i x[m][i]*Wih[dir][j][i] + b[j]
// p = hh*4 + gate for j = gate*64+hh.
// 148 CTAs (1/SM), 512 threads. CTA owns one dir's W (permuted, smem,
// loaded ONCE) and loops over m-tiles of 128 rows with register-prefetched
// x tiles. Thread tile: 8m x 8p (4 f32x2 accs x 8 rows).
// =======================================================================
__global__ void __launch_bounds__(512, 1) gates_gemm(
    const float* __restrict__ x,
    const float* __restrict__ Wf, const float* __restrict__ bf,
    const float* __restrict__ Wb, const float* __restrict__ bb)
{
    extern __shared__ float sm[];
    float* W_s = sm;                  // [128 k][256 p]
    float* x_s = sm + 128 * 256;      // [128 m][129]
    float* b_s = x_s + 128 * 129;     // [256 p]

    const int tid  = threadIdx.x;
    const int dir  = blockIdx.x & 1;
    const int cpos = blockIdx.x >> 1;   // 0..73

    const float* W    = dir ? Wb : Wf;
    const float* bias = dir ? bb : bf;

    // load W permuted (once): 256 rows, each thread does half a row
    {
        const int j  = tid >> 1;
        const int hr = tid & 1;
        const int p  = ((j & 63) << 2) | (j >> 6);
        const float4* wr = (const float4*)(W + j * IN_ + hr * 64);
#pragma unroll
        for (int iq = 0; iq < 16; iq++) {
            float4 v = wr[iq];
            const int i = hr * 64 + iq * 4;
            W_s[(i + 0) * 256 + p] = v.x;
            W_s[(i + 1) * 256 + p] = v.y;
            W_s[(i + 2) * 256 + p] = v.z;
            W_s[(i + 3) * 256 + p] = v.w;
        }
        if (hr == 0) b_s[p] = bias[j];
    }

    const int mg = tid & 15;   // 16 groups x 8 m
    const int ng = tid >> 4;   // 32 groups x 8 p

    const float* xrow = x_s + mg * 8 * 129;
    const float* wcol = W_s + ng * 8;

    // prefetch first x tile into registers (tile is contiguous in gmem)
    float4 xr[8];
    {
        const float4* src = (const float4*)x + (size_t)cpos * 128 * 32;
#pragma unroll
        for (int q = 0; q < 8; q++) xr[q] = src[tid + q * 512];
    }

    for (int mt = cpos; mt < BT_ / 128; mt += 74) {
        __syncthreads();   // x_s free (and W_s ready on first iter)
        // stage x tile to smem
#pragma unroll
        for (int q = 0; q < 8; q++) {
            const int f = tid + q * 512;
            float* d = x_s + (f >> 5) * 129 + (f & 31) * 4;
            d[0] = xr[q].x; d[1] = xr[q].y; d[2] = xr[q].z; d[3] = xr[q].w;
        }
        __syncthreads();

        // prefetch next tile
        const int mtn = mt + 74;
        if (mtn < BT_ / 128) {
            const float4* src = (const float4*)x + (size_t)mtn * 128 * 32;
#pragma unroll
            for (int q = 0; q < 8; q++) xr[q] = src[tid + q * 512];
        }

        unsigned long long acc[8][4];
#pragma unroll
        for (int r = 0; r < 8; r++)
#pragma unroll
            for (int c = 0; c < 4; c++) acc[r][c] = 0ULL;

#pragma unroll 4
        for (int k = 0; k < 128; k++) {
            ulonglong2 wA = *(const ulonglong2*)(wcol + k * 256);
            ulonglong2 wB = *(const ulonglong2*)(wcol + k * 256 + 4);
#pragma unroll
            for (int r = 0; r < 8; r++) {
                unsigned long long a = splat2(xrow[r * 129 + k]);
                acc[r][0] = ffma2(a, wA.x, acc[r][0]);
                acc[r][1] = ffma2(a, wA.y, acc[r][1]);
                acc[r][2] = ffma2(a, wB.x, acc[r][2]);
                acc[r][3] = ffma2(a, wB.y, acc[r][3]);
            }
        }

        // bias + store
        const size_t m0 = (size_t)mt * 128;
#pragma unroll
        for (int r = 0; r < 8; r++) {
            float* orow = g_G + ((size_t)dir * BT_ + m0 + mg * 8 + r) * NG_ + ng * 8;
            float f0, f1, f2, f3;
            unpack2(acc[r][0], f0, f1);
            unpack2(acc[r][1], f2, f3);
            f0 += b_s[ng * 8 + 0];
            f1 += b_s[ng * 8 + 1];
            f2 += b_s[ng * 8 + 2];
            f3 += b_s[ng * 8 + 3];
            *(float4*)orow = make_float4(f0, f1, f2, f3);
            unpack2(acc[r][2], f0, f1);
            unpack2(acc[r][3], f2, f3);
            f0 += b_s[ng * 8 + 4];
            f1 += b_s[ng * 8 + 5];
            f2 += b_s[ng * 8 + 6];
            f3 += b_s[ng * 8 + 7];
            *(float4*)(orow + 4) = make_float4(f0, f1, f2, f3);
        }
    }
}

// =======================================================================
// Kernel 2: recurrence. 256 CTAs = (2 dirs) x (128 batch-chunks of 4),
// 2 CTAs/SM so independent CTAs fill each other's barrier/MUFU bubbles.
// 256 threads: matvec thread = gate-row j (Whh[j][:] in regs), 4 batches
// via 2 f32x2 accumulators; epilogue thread = one (b,hh) unit.
// =======================================================================
__global__ void __launch_bounds__(256, 2) lstm_rec(
    const float* __restrict__ Whh_f, const float* __restrict__ Whh_b,
    float* __restrict__ out)
{
    __shared__ __align__(16) float h_s[64][4];   // [k][b]
    __shared__ __align__(16) float gq[4][256];   // [b][hh*4+gate]

    const int tid = threadIdx.x;
    const int dir = blockIdx.x >> 7;
    const int b0  = (blockIdx.x & 127) << 2;

    const float* Whh = dir ? Whh_b : Whh_f;

    const int j  = tid;
    const int pj = ((j & 63) << 2) | (j >> 6);

    float w[64];
#pragma unroll
    for (int k = 0; k < 64; k++) w[k] = Whh[j * 64 + k];

    const int b_e  = tid >> 6;   // 0..3
    const int hh_e = tid & 63;   // 0..63

    ((float*)h_s)[tid] = 0.f;
    float c = 0.f;
    __syncthreads();

    const size_t xg_base =
        ((size_t)dir * BT_ + (size_t)(b0 + b_e) * T_) * NG_ + (size_t)(hh_e << 2);
    float* out_base = out + (size_t)(b0 + b_e) * T_ * 128 + dir * 64 + hh_e;

    for (int s = 0; s < T_; s++) {
        const int t = dir ? (T_ - 1 - s) : s;

        // prefetch xg for this step's epilogue (hidden behind the matvec)
        float4 xa = *(const float4*)(g_G + xg_base + (size_t)t * NG_);

        // g[b][j] = sum_k h[b][k] * w[k], 4 batches packed as 2 f32x2
        unsigned long long a0 = 0, a1 = 0;
#pragma unroll
        for (int k = 0; k < 64; k++) {
            ulonglong2 hv = *(const ulonglong2*)&h_s[k][0];
            unsigned long long wv = splat2(w[k]);
            a0 = ffma2(hv.x, wv, a0);
            a1 = ffma2(hv.y, wv, a1);
        }
        {
            float g0, g1, g2, g3;
            unpack2(a0, g0, g1);
            unpack2(a1, g2, g3);
            gq[0][pj] = g0;
            gq[1][pj] = g1;
            gq[2][pj] = g2;
            gq[3][pj] = g3;
        }
        __syncthreads();

        // activation: one (b_e, hh_e) unit per thread
        float4 ga = *(const float4*)&gq[b_e][hh_e << 2];
        float gi = ga.x + xa.x;
        float gf = ga.y + xa.y;
        float gg = ga.z + xa.z;
        float go = ga.w + xa.w;

        c = sig_fast(gf) * c + sig_fast(gi) * tanh_fast(gg);
        float h = sig_fast(go) * tanh_fast(c);

        h_s[hh_e][b_e] = h;
        out_base[(size_t)t * 128] = h;
        __syncthreads();
    }
}

// =======================================================================
extern "C" void kernel_launch(void* const* d_in, const int* in_sizes, int n_in,
                              void* d_out, int out_size)
{
    const float* x    = (const float*)d_in[0];
    const float* Wihf = (const float*)d_in[1];
    const float* Whhf = (const float*)d_in[2];
    const float* bf   = (const float*)d_in[3];
    const float* Wihb = (const float*)d_in[4];
    const float* Whhb = (const float*)d_in[5];
    const float* bb   = (const float*)d_in[6];
    float* out = (float*)d_out;

    const int smem = (128 * 256 + 128 * 129 + 256) * 4;  // 198144 B
    cudaFuncSetAttribute(gates_gemm, cudaFuncAttributeMaxDynamicSharedMemorySize, smem);

    gates_gemm<<<148, 512, smem>>>(x, Wihf, bf, Wihb, bb);
    lstm_rec<<<256, 256>>>(Whhf, Whhb, out);
}

// round 5
// speedup vs baseline: 1.3366x; 1.1493x over previous
#include <cuda_runtime.h>
#include <cstdint>

#define B_  512
#define T_  1024
#define IN_ 128
#define H_  64
#define NG_ 256
#define BT_ (B_ * T_)
#define TILES_ (BT_ / 128)   // 4096 m-tiles per dir

// xg scratch: [dir][b*T+t][hh*4 + slot], slot: 0=i,1=g,2=f,3=o  (1 GiB)
__device__ float g_G[(size_t)2 * BT_ * NG_];

// ---------------- f32x2 helpers ----------------
__device__ __forceinline__ unsigned long long ffma2(unsigned long long a,
                                                    unsigned long long b,
                                                    unsigned long long c) {
    unsigned long long d;
    asm("fma.rn.f32x2 %0, %1, %2, %3;" : "=l"(d) : "l"(a), "l"(b), "l"(c));
    return d;
}
__device__ __forceinline__ float red2(unsigned long long v) {
    unsigned int a, b;
    asm("mov.b64 {%0, %1}, %2;" : "=r"(a), "=r"(b) : "l"(v));
    return __uint_as_float(a) + __uint_as_float(b);
}

// ---------------- activations (MUFU tanh) ----------------
__device__ __forceinline__ float tanh_fast(float x) {
    float y;
    asm("tanh.approx.f32 %0, %1;" : "=f"(y) : "f"(x));
    return y;
}
__device__ __forceinline__ float sig_fast(float x) {
    return fmaf(tanh_fast(0.5f * x), 0.5f, 0.5f);
}

// ---------------- cp.async ----------------
__device__ __forceinline__ void cp_async16(uint32_t dst, const void* src) {
    asm volatile("cp.async.cg.shared.global [%0], [%1], 16;" :: "r"(dst), "l"(src));
}
__device__ __forceinline__ void cp_commit() {
    asm volatile("cp.async.commit_group;");
}
__device__ __forceinline__ void cp_wait0() {
    asm volatile("cp.async.wait_group 0;");
}

// =======================================================================
// Kernel 1 (persistent GEMM): xg[dir][m][p] = sum_i x[m][i]*W[j][i] + b[j]
// p = hh*4 + slot(gate), slot map {i,f,g,o} -> {0,2,1,3}.
// 148 CTAs x 256 thr. W_s[p][k] transposed (stride 132, phase-conflict-free
// LDS.128); x_s[m][k] read as uniform broadcast; k-split FFMA2 (no MOVs).
// Warp tile 8m x 256p, 2 m-passes per 128-row tile. cp.async x prefetch.
// =======================================================================
__global__ void __launch_bounds__(256, 1) gates_gemm(
    const float* __restrict__ x,
    const float* __restrict__ Wf, const float* __restrict__ bf,
    const float* __restrict__ Wb, const float* __restrict__ bb)
{
    extern __shared__ float sm[];
    float* W_s = sm;                    // [256 p][132]
    float* x_s = sm + 256 * 132;        // [128 m][128 k]
    float* b_s = x_s + 128 * 128;       // [256 p]

    const int tid  = threadIdx.x;
    const int dir  = blockIdx.x & 1;
    const int cpos = blockIdx.x >> 1;   // 0..73

    const float* W    = dir ? Wb : Wf;
    const float* bias = dir ? bb : bf;

    // load W transposed + permuted: W_s[p][k] = W[j][k]
    {
        const int j = tid;
        const int g = j >> 6;
        const int gp = ((g + 1) & 2) ? (g ^ 3) : g;   // {0,2,1,3}
        const int p = ((j & 63) << 2) | gp;
        const float4* wr = (const float4*)(W + j * IN_);
        float* dst = W_s + p * 132;
#pragma unroll
        for (int q = 0; q < 32; q++) {
            float4 v = wr[q];
            dst[4 * q + 0] = v.x;
            dst[4 * q + 1] = v.y;
            dst[4 * q + 2] = v.z;
            dst[4 * q + 3] = v.w;
        }
        b_s[p] = bias[j];
    }

    const int w = tid >> 5;   // warp 0..7 -> 8 m-rows within pass
    const int l = tid & 31;   // lane -> p = 32g + l

    const uint32_t xs_u32 = (uint32_t)__cvta_generic_to_shared(x_s);

    // prefetch first x tile (64KB: 4096 float4, 16 per thread)
    {
        const float4* src = (const float4*)x + (size_t)cpos * 128 * 32;
#pragma unroll
        for (int i = 0; i < 16; i++)
            cp_async16(xs_u32 + (tid + i * 256) * 16, src + tid + i * 256);
        cp_commit();
    }

    __syncthreads();   // W_s / b_s ready

    float br[8];
#pragma unroll
    for (int g = 0; g < 8; g++) br[g] = b_s[g * 32 + l];

    for (int mt = cpos; mt < TILES_; mt += 74) {
        cp_wait0();
        __syncthreads();   // x_s ready

#pragma unroll
        for (int pass = 0; pass < 2; pass++) {
            unsigned long long acc[8][8];
#pragma unroll
            for (int r = 0; r < 8; r++)
#pragma unroll
                for (int g = 0; g < 8; g++) acc[r][g] = 0ULL;

            const float* xb = x_s + (pass * 64 + w * 8) * 128;

#pragma unroll 2
            for (int q = 0; q < 32; q++) {
                ulonglong2 wq[8];
#pragma unroll
                for (int g = 0; g < 8; g++)
                    wq[g] = *(const ulonglong2*)(W_s + (g * 32 + l) * 132 + 4 * q);
#pragma unroll
                for (int r = 0; r < 8; r++) {
                    ulonglong2 xq = *(const ulonglong2*)(xb + r * 128 + 4 * q);
#pragma unroll
                    for (int g = 0; g < 8; g++) {
                        acc[r][g] = ffma2(xq.x, wq[g].x, acc[r][g]);
                        acc[r][g] = ffma2(xq.y, wq[g].y, acc[r][g]);
                    }
                }
            }

            // reduce + bias + store
#pragma unroll
            for (int r = 0; r < 8; r++) {
                const size_t m = (size_t)mt * 128 + pass * 64 + w * 8 + r;
                float* orow = g_G + ((size_t)dir * BT_ + m) * NG_;
#pragma unroll
                for (int g = 0; g < 8; g++)
                    orow[g * 32 + l] = red2(acc[r][g]) + br[g];
            }
        }

        __syncthreads();   // done reading x_s
        const int mtn = mt + 74;
        if (mtn < TILES_) {
            const float4* src = (const float4*)x + (size_t)mtn * 128 * 32;
#pragma unroll
            for (int i = 0; i < 16; i++)
                cp_async16(xs_u32 + (tid + i * 256) * 16, src + tid + i * 256);
        }
        cp_commit();
    }
}

// =======================================================================
// Kernel 2: recurrence. 256 CTAs = (2 dirs) x (128 chunks of 4 batches),
// 128 threads, 2 CTAs/SM.
// Thread = (hh = tid>>1, type = tid&1): owns 2 gate rows of hh:
//   type0: j = hh (i), 128+hh (g);  type1: j = 64+hh (f), 192+hh (o).
// Whh rows k-pair-packed in regs (u64), h_s[buf][b][k] broadcast LDS.128
// feeds 2j x 4k per load (k-split FFMA2, zero MOVs). Gate exchange via one
// shfl.xor(1); branchless sig/tanh select; c,h live in type1; double-
// buffered h_s -> ONE barrier per step.
// =======================================================================
__global__ void __launch_bounds__(128, 2) lstm_rec(
    const float* __restrict__ Whh_f, const float* __restrict__ Whh_b,
    float* __restrict__ out)
{
    __shared__ __align__(16) float h_s[2][4][64];

    const int tid  = threadIdx.x;
    const int dir  = blockIdx.x >> 7;
    const int b0   = (blockIdx.x & 127) << 2;
    const int hh   = tid >> 1;
    const int type = tid & 1;

    const float* Whh = dir ? Whh_b : Whh_f;

    const int j0 = type ? (64 + hh) : hh;          // i or f
    const int j1 = j0 + 128;                       // g or o

    // k-pair packed weights: w2[m] = (w[2m], w[2m+1])
    unsigned long long w2a[32], w2b[32];
    {
        const ulonglong2* ra = (const ulonglong2*)(Whh + j0 * 64);
        const ulonglong2* rb = (const ulonglong2*)(Whh + j1 * 64);
#pragma unroll
        for (int i = 0; i < 16; i++) {
            ulonglong2 va = ra[i], vb = rb[i];
            w2a[2 * i] = va.x; w2a[2 * i + 1] = va.y;
            w2b[2 * i] = vb.x; w2b[2 * i + 1] = vb.y;
        }
    }

    // branchless activation constants:
    // t1v = tanh(g1*s1)*m1 + c1 : type0 -> tanh(g1), type1 -> sigmoid(g1)
    const float s1 = type ? 0.5f : 1.0f;
    const float m1 = type ? 0.5f : 1.0f;
    const float c1 = type ? 0.5f : 0.0f;

    // init h buffers
#pragma unroll
    for (int i = 0; i < 4; i++) ((float*)h_s)[tid + i * 128] = 0.f;
    float c[4] = {0.f, 0.f, 0.f, 0.f};
    __syncthreads();

    // xg: float2 at [dir][b][t][hh*4 + type*2]
    const size_t xgb = ((size_t)dir * BT_) * NG_ + (size_t)hh * 4 + type * 2;
    float* outb = out + dir * 64 + hh;

    for (int s = 0; s < T_; s++) {
        const int t = dir ? (T_ - 1 - s) : s;

        // prefetch xg for this step (consumed after the matvec)
        float2 xg[4];
#pragma unroll
        for (int b = 0; b < 4; b++)
            xg[b] = *(const float2*)(g_G + xgb + ((size_t)(b0 + b) * T_ + t) * NG_);

        const float* cur = &h_s[s & 1][0][0];
        float* nxt = &h_s[(s & 1) ^ 1][0][0];

        unsigned long long a0[4] = {0, 0, 0, 0}, a1[4] = {0, 0, 0, 0};
#pragma unroll
        for (int q = 0; q < 16; q++) {
#pragma unroll
            for (int b = 0; b < 4; b++) {
                ulonglong2 hb = *(const ulonglong2*)(cur + b * 64 + 4 * q);
                a0[b] = ffma2(hb.x, w2a[2 * q], a0[b]);
                a0[b] = ffma2(hb.y, w2a[2 * q + 1], a0[b]);
                a1[b] = ffma2(hb.x, w2b[2 * q], a1[b]);
                a1[b] = ffma2(hb.y, w2b[2 * q + 1], a1[b]);
            }
        }

#pragma unroll
        for (int b = 0; b < 4; b++) {
            const float g0 = red2(a0[b]) + xg[b].x;   // i or f gate
            const float g1 = red2(a1[b]) + xg[b].y;   // g or o gate

            const float t0  = sig_fast(g0);                       // sig(i) / sig(f)
            const float t1v = fmaf(tanh_fast(g1 * s1), m1, c1);   // tanh(g) / sig(o)

            const float v  = t0 * t1v;                 // type0: sig(i)*tanh(g)
            const float vr = __shfl_xor_sync(0xFFFFFFFFu, v, 1);

            // meaningful on type1 only (type0 lanes compute garbage, unused)
            c[b] = fmaf(t0, c[b], vr);                 // sig(f)*c + sig(i)*tanh(g)
            const float h = t1v * tanh_fast(c[b]);     // sig(o)*tanh(c)

            if (type) {
                nxt[b * 64 + hh] = h;
                outb[((size_t)(b0 + b) * T_ + t) * 128] = h;
            }
        }
        __syncthreads();
    }
}

// =======================================================================
extern "C" void kernel_launch(void* const* d_in, const int* in_sizes, int n_in,
                              void* d_out, int out_size)
{
    const float* x    = (const float*)d_in[0];
    const float* Wihf = (const float*)d_in[1];
    const float* Whhf = (const float*)d_in[2];
    const float* bf   = (const float*)d_in[3];
    const float* Wihb = (const float*)d_in[4];
    const float* Whhb = (const float*)d_in[5];
    const float* bb   = (const float*)d_in[6];
    float* out = (float*)d_out;

    const int smem = (256 * 132 + 128 * 128 + 256) * 4;  // 201728 B
    cudaFuncSetAttribute(gates_gemm, cudaFuncAttributeMaxDynamicSharedMemorySize, smem);

    gates_gemm<<<148, 256, smem>>>(x, Wihf, bf, Wihb, bb);
    lstm_rec<<<256, 128>>>(Whhf, Whhb, out);
}

// round 6
// speedup vs baseline: 1.6178x; 1.2104x over previous
#include <cuda_runtime.h>
#include <cstdint>

#define B_  512
#define T_  1024
#define IN_ 128
#define H_  64
#define NG_ 256
#define BT_ (B_ * T_)
#define XTILES_ (BT_ / 64)   // 8192 x-tiles of 64 rows per dir

// xg scratch: [dir][b*T+t][hh*4 + slot], slot: 0=i,1=g,2=f,3=o  (1 GiB)
__device__ float g_G[(size_t)2 * BT_ * NG_];

// ---------------- f32x2 helpers ----------------
__device__ __forceinline__ unsigned long long ffma2(unsigned long long a,
                                                    unsigned long long b,
                                                    unsigned long long c) {
    unsigned long long d;
    asm("fma.rn.f32x2 %0, %1, %2, %3;" : "=l"(d) : "l"(a), "l"(b), "l"(c));
    return d;
}
__device__ __forceinline__ float red2(unsigned long long v) {
    unsigned int a, b;
    asm("mov.b64 {%0, %1}, %2;" : "=r"(a), "=r"(b) : "l"(v));
    return __uint_as_float(a) + __uint_as_float(b);
}

// ---------------- activations (MUFU tanh) ----------------
__device__ __forceinline__ float tanh_fast(float x) {
    float y;
    asm("tanh.approx.f32 %0, %1;" : "=f"(y) : "f"(x));
    return y;
}
__device__ __forceinline__ float sig_fast(float x) {
    return fmaf(tanh_fast(0.5f * x), 0.5f, 0.5f);
}

// ---------------- cp.async ----------------
__device__ __forceinline__ void cp_async16(uint32_t dst, const void* src) {
    asm volatile("cp.async.cg.shared.global [%0], [%1], 16;" :: "r"(dst), "l"(src));
}
__device__ __forceinline__ void cp_async8(uint32_t dst, const void* src) {
    asm volatile("cp.async.ca.shared.global [%0], [%1], 8;" :: "r"(dst), "l"(src));
}
__device__ __forceinline__ void cp_commit() {
    asm volatile("cp.async.commit_group;");
}
__device__ __forceinline__ void cp_wait1() {
    asm volatile("cp.async.wait_group 1;");
}

// =======================================================================
// Kernel 1 (persistent GEMM): xg[dir][m][p] = sum_i x[m][i]*W[j][i] + b[j]
// p = hh*4 + slot(gate), slot map {i,f,g,o} -> {0,2,1,3}.
// 148 CTAs x 256 thr. W_s[p][k] (stride 132, phase-conflict-free LDS.128)
// resident for the whole kernel. x double-buffered 64-row tiles via
// cp.async (distance-1 pipeline). Per g-half: acc 8m x 4g u64 (64 regs,
// no spill). k-split FFMA2, x as uniform broadcast LDS.128.
// =======================================================================
__global__ void __launch_bounds__(256, 1) gates_gemm(
    const float* __restrict__ x,
    const float* __restrict__ Wf, const float* __restrict__ bf,
    const float* __restrict__ Wb, const float* __restrict__ bb)
{
    extern __shared__ float sm[];
    float* W_s = sm;                    // [256 p][132]
    float* x_s = sm + 256 * 132;        // [2][64 m][128 k]
    float* b_s = x_s + 2 * 64 * 128;    // [256 p]

    const int tid  = threadIdx.x;
    const int dir  = blockIdx.x & 1;
    const int cpos = blockIdx.x >> 1;   // 0..73

    const float* W    = dir ? Wb : Wf;
    const float* bias = dir ? bb : bf;

    // load W transposed + permuted: W_s[p][k] = W[j][k]
    {
        const int j = tid;
        const int g = j >> 6;
        const int gp = ((g + 1) & 2) ? (g ^ 3) : g;   // {0,2,1,3}
        const int p = ((j & 63) << 2) | gp;
        const float4* wr = (const float4*)(W + j * IN_);
        float* dst = W_s + p * 132;
#pragma unroll
        for (int q = 0; q < 32; q++) {
            float4 v = wr[q];
            dst[4 * q + 0] = v.x;
            dst[4 * q + 1] = v.y;
            dst[4 * q + 2] = v.z;
            dst[4 * q + 3] = v.w;
        }
        b_s[p] = bias[j];
    }

    const int w = tid >> 5;   // warp -> 8 m rows
    const int l = tid & 31;   // lane -> p = 32*g + l

    const uint32_t xs_u32 = (uint32_t)__cvta_generic_to_shared(x_s);

    // prologue: prefetch first tile into buf 0 (32KB = 2048 float4)
    {
        const float4* src = (const float4*)x + (size_t)cpos * 2048;
#pragma unroll
        for (int i = 0; i < 8; i++)
            cp_async16(xs_u32 + (tid + i * 256) * 16, src + tid + i * 256);
        cp_commit();
    }

    __syncthreads();   // W_s / b_s ready (covers first-tile too via waits below)

    float br[8];
#pragma unroll
    for (int g = 0; g < 8; g++) br[g] = b_s[g * 32 + l];

    int it = 0;
    for (int mt = cpos; mt < XTILES_; mt += 74, it++) {
        // prefetch next tile into the other buffer
        const int mtn = mt + 74;
        if (mtn < XTILES_) {
            const uint32_t dst = xs_u32 + ((it + 1) & 1) * 32768;
            const float4* src = (const float4*)x + (size_t)mtn * 2048;
#pragma unroll
            for (int i = 0; i < 8; i++)
                cp_async16(dst + (tid + i * 256) * 16, src + tid + i * 256);
        }
        cp_commit();
        cp_wait1();        // current tile's group complete
        __syncthreads();   // visible to all; prev-tile reads done

        const float* xb = x_s + (it & 1) * 8192 + (w * 8) * 128;

#pragma unroll
        for (int gh = 0; gh < 2; gh++) {
            unsigned long long acc[8][4];
#pragma unroll
            for (int r = 0; r < 8; r++)
#pragma unroll
                for (int gi = 0; gi < 4; gi++) acc[r][gi] = 0ULL;

#pragma unroll 2
            for (int q = 0; q < 32; q++) {
                ulonglong2 wq[4];
#pragma unroll
                for (int gi = 0; gi < 4; gi++)
                    wq[gi] = *(const ulonglong2*)(W_s + ((gh * 4 + gi) * 32 + l) * 132 + 4 * q);
#pragma unroll
                for (int r = 0; r < 8; r++) {
                    ulonglong2 xq = *(const ulonglong2*)(xb + r * 128 + 4 * q);
#pragma unroll
                    for (int gi = 0; gi < 4; gi++) {
                        acc[r][gi] = ffma2(xq.x, wq[gi].x, acc[r][gi]);
                        acc[r][gi] = ffma2(xq.y, wq[gi].y, acc[r][gi]);
                    }
                }
            }

            // reduce + bias + store
#pragma unroll
            for (int r = 0; r < 8; r++) {
                const size_t m = (size_t)mt * 64 + w * 8 + r;
                float* orow = g_G + ((size_t)dir * BT_ + m) * NG_ + gh * 128;
#pragma unroll
                for (int gi = 0; gi < 4; gi++)
                    orow[gi * 32 + l] = red2(acc[r][gi]) + br[gh * 4 + gi];
            }
        }

        __syncthreads();   // done reading this buffer before it is refilled
    }
}

// =======================================================================
// Kernel 2: recurrence. 256 CTAs = (2 dirs) x (128 chunks of 4 batches),
// 128 threads, 2 CTAs/SM.
// Thread = (hh = tid>>1, type = tid&1): owns 2 gate rows of hh:
//   type0: i & g rows;  type1: f & o rows. Whh k-pair packed in regs.
// xg prefetched ONE FULL STEP ahead via cp.async double buffer (no LDG
// latency exposure, no BAR reordering issue). Gate exchange via one
// shfl.xor(1); double-buffered h_s -> ONE barrier per step.
// =======================================================================
__global__ void __launch_bounds__(128, 2) lstm_rec(
    const float* __restrict__ Whh_f, const float* __restrict__ Whh_b,
    float* __restrict__ out)
{
    __shared__ __align__(16) float h_s[2][4][64];
    __shared__ __align__(16) float2 xg_s[2][4][128];

    const int tid  = threadIdx.x;
    const int dir  = blockIdx.x >> 7;
    const int b0   = (blockIdx.x & 127) << 2;
    const int hh   = tid >> 1;
    const int type = tid & 1;

    const float* Whh = dir ? Whh_b : Whh_f;

    const int j0 = type ? (64 + hh) : hh;          // i or f
    const int j1 = j0 + 128;                       // g or o

    unsigned long long w2a[32], w2b[32];
    {
        const ulonglong2* ra = (const ulonglong2*)(Whh + j0 * 64);
        const ulonglong2* rb = (const ulonglong2*)(Whh + j1 * 64);
#pragma unroll
        for (int i = 0; i < 16; i++) {
            ulonglong2 va = ra[i], vb = rb[i];
            w2a[2 * i] = va.x; w2a[2 * i + 1] = va.y;
            w2b[2 * i] = vb.x; w2b[2 * i + 1] = vb.y;
        }
    }

    const float s1 = type ? 0.5f : 1.0f;
    const float m1 = type ? 0.5f : 1.0f;
    const float c1 = type ? 0.5f : 0.0f;

#pragma unroll
    for (int i = 0; i < 4; i++) ((float*)h_s)[tid + i * 128] = 0.f;
    float c[4] = {0.f, 0.f, 0.f, 0.f};

    // xg source: float2 at [dir][b0+b][t][hh*4 + type*2]
    const float* xg_src = g_G + ((size_t)dir * BT_) * NG_ + (size_t)hh * 4 + type * 2;
    const uint32_t xgs_u32 = (uint32_t)__cvta_generic_to_shared(&xg_s[0][0][0]);
    float* outb = out + dir * 64 + hh;

    // prologue: prefetch step 0 into buf 0
    {
        const int t0 = dir ? (T_ - 1) : 0;
#pragma unroll
        for (int b = 0; b < 4; b++)
            cp_async8(xgs_u32 + (b * 128 + tid) * 8,
                      xg_src + ((size_t)(b0 + b) * T_ + t0) * NG_);
        cp_commit();
    }
    __syncthreads();

    for (int s = 0; s < T_; s++) {
        const int t = dir ? (T_ - 1 - s) : s;

        // prefetch xg for step s+1 into the other buffer
        if (s + 1 < T_) {
            const int tn = dir ? (T_ - 2 - s) : (s + 1);
            const uint32_t dst = xgs_u32 + ((s + 1) & 1) * 4096;
#pragma unroll
            for (int b = 0; b < 4; b++)
                cp_async8(dst + (b * 128 + tid) * 8,
                          xg_src + ((size_t)(b0 + b) * T_ + tn) * NG_);
        }
        cp_commit();

        const float* cur = &h_s[s & 1][0][0];
        float* nxt = &h_s[(s & 1) ^ 1][0][0];

        unsigned long long a0[4] = {0, 0, 0, 0}, a1[4] = {0, 0, 0, 0};
#pragma unroll
        for (int q = 0; q < 16; q++) {
#pragma unroll
            for (int b = 0; b < 4; b++) {
                ulonglong2 hb = *(const ulonglong2*)(cur + b * 64 + 4 * q);
                a0[b] = ffma2(hb.x, w2a[2 * q], a0[b]);
                a0[b] = ffma2(hb.y, w2a[2 * q + 1], a0[b]);
                a1[b] = ffma2(hb.x, w2b[2 * q], a1[b]);
                a1[b] = ffma2(hb.y, w2b[2 * q + 1], a1[b]);
            }
        }

        cp_wait1();   // step s's xg group complete (s+1's may pend)

#pragma unroll
        for (int b = 0; b < 4; b++) {
            const float2 xg = xg_s[s & 1][b][tid];
            const float g0 = red2(a0[b]) + xg.x;   // i or f gate
            const float g1 = red2(a1[b]) + xg.y;   // g or o gate

            const float t0  = sig_fast(g0);                       // sig(i)/sig(f)
            const float t1v = fmaf(tanh_fast(g1 * s1), m1, c1);   // tanh(g)/sig(o)

            const float v  = t0 * t1v;
            const float vr = __shfl_xor_sync(0xFFFFFFFFu, v, 1);

            c[b] = fmaf(t0, c[b], vr);                 // valid on type1
            const float h = t1v * tanh_fast(c[b]);

            if (type) {
                nxt[b * 64 + hh] = h;
                outb[((size_t)(b0 + b) * T_ + t) * 128] = h;
            }
        }
        __syncthreads();
    }
}

// =======================================================================
extern "C" void kernel_launch(void* const* d_in, const int* in_sizes, int n_in,
                              void* d_out, int out_size)
{
    const float* x    = (const float*)d_in[0];
    const float* Wihf = (const float*)d_in[1];
    const float* Whhf = (const float*)d_in[2];
    const float* bf   = (const float*)d_in[3];
    const float* Wihb = (const float*)d_in[4];
    const float* Whhb = (const float*)d_in[5];
    const float* bb   = (const float*)d_in[6];
    float* out = (float*)d_out;

    const int smem = (256 * 132 + 2 * 64 * 128 + 256) * 4;  // 201728 B
    cudaFuncSetAttribute(gates_gemm, cudaFuncAttributeMaxDynamicSharedMemorySize, smem);

    gates_gemm<<<148, 256, smem>>>(x, Wihf, bf, Wihb, bb);
    lstm_rec<<<256, 128>>>(Whhf, Whhb, out);
}

// round 8
// speedup vs baseline: 1.9788x; 1.2231x over previous
#include <cuda_runtime.h>
#include <cuda_bf16.h>
#include <cstdint>

#define B_  512
#define T_  1024
#define IN_ 128
#define NG_ 256
#define BT_ (B_ * T_)
#define MTILES 4096          // BT_/128 m-tiles per dir

// xg scratch: [dir][b*T+t][hh*4 + slot], slot: 0=i,1=g,2=f,3=o  (1 GiB)
__device__ float g_G[(size_t)2 * BT_ * NG_];

// ---------------- smem map (bytes) for gates_gemm ----------------
// bf16 tiles, row stride 136 elems = 272 B (conflict-free ldmatrix)
#define XSTRIDE 272
#define SM_XHI  0
#define SM_XLO  (SM_XHI + 128 * XSTRIDE)     //  34816
#define SM_WHI  (SM_XLO + 128 * XSTRIDE)     //  69632
#define SM_WLO  (SM_WHI + 256 * XSTRIDE)     // 139264
#define SM_BIAS (SM_WLO + 256 * XSTRIDE)     // 208896
#define SM_TOTAL (SM_BIAS + 1024)            // 209920

// ---------------- ptx helpers ----------------
__device__ __forceinline__ uint32_t smem_u32(const void* p) {
    return (uint32_t)__cvta_generic_to_shared(p);
}
__device__ __forceinline__ void ldsm4(uint32_t* r, uint32_t addr) {
    asm volatile("ldmatrix.sync.aligned.m8n8.x4.shared.b16 {%0,%1,%2,%3}, [%4];"
                 : "=r"(r[0]), "=r"(r[1]), "=r"(r[2]), "=r"(r[3]) : "r"(addr));
}
__device__ __forceinline__ void mma16816(float* c, const uint32_t* a,
                                         uint32_t b0, uint32_t b1) {
    asm volatile(
        "mma.sync.aligned.m16n8k16.row.col.f32.bf16.bf16.f32 "
        "{%0,%1,%2,%3}, {%4,%5,%6,%7}, {%8,%9}, {%0,%1,%2,%3};"
        : "+f"(c[0]), "+f"(c[1]), "+f"(c[2]), "+f"(c[3])
        : "r"(a[0]), "r"(a[1]), "r"(a[2]), "r"(a[3]), "r"(b0), "r"(b1));
}

// bf16x2 pack: low half = lo arg, high half = hi arg
__device__ __forceinline__ uint32_t pack_bf16x2(float lo, float hi) {
    uint32_t r;
    asm("cvt.rn.bf16x2.f32 %0, %1, %2;" : "=r"(r) : "f"(hi), "f"(lo));
    return r;
}
// hi/lo split of two floats -> packed bf16x2 hi + residual bf16x2 lo
__device__ __forceinline__ void split2(float a, float b, uint32_t& hi, uint32_t& lo) {
    hi = pack_bf16x2(a, b);
    float ra = a - __uint_as_float(hi << 16);
    float rb = b - __uint_as_float(hi & 0xFFFF0000u);
    lo = pack_bf16x2(ra, rb);
}

// ---------------- activations (MUFU tanh) ----------------
__device__ __forceinline__ float tanh_fast(float x) {
    float y;
    asm("tanh.approx.f32 %0, %1;" : "=f"(y) : "f"(x));
    return y;
}
__device__ __forceinline__ float sig_fast(float x) {
    return fmaf(tanh_fast(0.5f * x), 0.5f, 0.5f);
}

// ---------------- f32x2 / cp.async (recurrence) ----------------
__device__ __forceinline__ unsigned long long ffma2(unsigned long long a,
                                                    unsigned long long b,
                                                    unsigned long long c) {
    unsigned long long d;
    asm("fma.rn.f32x2 %0, %1, %2, %3;" : "=l"(d) : "l"(a), "l"(b), "l"(c));
    return d;
}
__device__ __forceinline__ float red2(unsigned long long v) {
    unsigned int a, b;
    asm("mov.b64 {%0, %1}, %2;" : "=r"(a), "=r"(b) : "l"(v));
    return __uint_as_float(a) + __uint_as_float(b);
}
__device__ __forceinline__ void cp_async8(uint32_t dst, const void* src) {
    asm volatile("cp.async.ca.shared.global [%0], [%1], 8;" :: "r"(dst), "l"(src));
}
__device__ __forceinline__ void cp_commit() {
    asm volatile("cp.async.commit_group;");
}
__device__ __forceinline__ void cp_wait1() {
    asm volatile("cp.async.wait_group 1;");
}

// =======================================================================
// Kernel 1: HMMA (mma.sync m16n8k16 bf16) split-precision GEMM.
// D[128m,256p] = x[128,128] @ W^T via 3 accumulating passes
//   xhi*Whi + xhi*Wlo + xlo*Whi (fp32 accs in registers).
// W rows stored at permuted p so D columns land in g_G's (hh,slot) order.
// 148 CTAs x 512 thr (16 warps): warp tile 32m x 64n -> 64 accs/thread.
// W split once per CTA; x split per tile. Tiles stride 74 per dir.
// =======================================================================
__global__ void __launch_bounds__(512, 1) gates_gemm(
    const float* __restrict__ x,
    const float* __restrict__ Wf, const float* __restrict__ bf,
    const float* __restrict__ Wb, const float* __restrict__ bb)
{
    extern __shared__ char sm[];
    const uint32_t smb = smem_u32(sm);

    const int tid  = threadIdx.x;
    const int wid  = tid >> 5;
    const int lane = tid & 31;
    const int dir  = blockIdx.x & 1;
    const int cpos = blockIdx.x >> 1;   // 0..73

    const float* W    = dir ? Wb : Wf;
    const float* bias = dir ? bb : bf;

    // ---- load + split W at permuted row p (once) ----
    {
        const int j    = tid >> 1;          // 0..255
        const int half = tid & 1;           // k half: cols 0-63 / 64-127
        const int g    = j >> 6;
        const int slot = (g == 0) ? 0 : (g == 1) ? 2 : (g == 2) ? 1 : 3;
        const int p    = ((j & 63) << 2) | slot;
        const float4* wr = (const float4*)(W + j * IN_ + half * 64);
        char* whi = sm + SM_WHI + p * XSTRIDE + half * 128;
        char* wlo = sm + SM_WLO + p * XSTRIDE + half * 128;
#pragma unroll
        for (int q = 0; q < 16; q++) {
            float4 v = wr[q];
            uint32_t h0, l0, h1, l1;
            split2(v.x, v.y, h0, l0);
            split2(v.z, v.w, h1, l1);
            *(uint2*)(whi + q * 8) = make_uint2(h0, h1);
            *(uint2*)(wlo + q * 8) = make_uint2(l0, l1);
        }
        if (half == 0) ((float*)(sm + SM_BIAS))[p] = bias[j];
    }

    // warp tiling
    const int msub  = (wid & 3) * 32;
    const int nsub0 = (wid >> 2) * 64;

    // ldmatrix lane address components
    const uint32_t aoff = (uint32_t)(msub + (lane & 15)) * XSTRIDE + (lane >> 4) * 16;
    const uint32_t boff = (uint32_t)(nsub0 + (lane & 7) + ((lane >> 4) << 3)) * XSTRIDE
                          + ((lane >> 3) & 1) * 16;

    const int r0c = tid >> 5;     // conversion row base
    const int lc  = tid & 31;     // conversion col4

    const int ntiles_end = MTILES;

    for (int mt = cpos; mt < ntiles_end; mt += 74) {
        __syncthreads();   // x smem free (first iter: W_s/bias done)

        // ---- load + split x tile ----
        {
            const float* srcb = x + (size_t)mt * 128 * IN_;
#pragma unroll
            for (int i = 0; i < 4; i++) {
                const int row0 = r0c + 32 * i;
                float4 v0 = *(const float4*)(srcb + (size_t)row0 * IN_ + lc * 4);
                float4 v1 = *(const float4*)(srcb + (size_t)(row0 + 16) * IN_ + lc * 4);
                uint32_t h0, l0, h1, l1;
                split2(v0.x, v0.y, h0, l0);
                split2(v0.z, v0.w, h1, l1);
                *(uint2*)(sm + SM_XHI + row0 * XSTRIDE + lc * 8) = make_uint2(h0, h1);
                *(uint2*)(sm + SM_XLO + row0 * XSTRIDE + lc * 8) = make_uint2(l0, l1);
                split2(v1.x, v1.y, h0, l0);
                split2(v1.z, v1.w, h1, l1);
                *(uint2*)(sm + SM_XHI + (row0 + 16) * XSTRIDE + lc * 8) = make_uint2(h0, h1);
                *(uint2*)(sm + SM_XLO + (row0 + 16) * XSTRIDE + lc * 8) = make_uint2(l0, l1);
            }
        }
        __syncthreads();

        // ---- 3-pass mma accumulate ----
        float acc[2][8][4];
#pragma unroll
        for (int m2 = 0; m2 < 2; m2++)
#pragma unroll
            for (int j = 0; j < 8; j++)
#pragma unroll
                for (int q = 0; q < 4; q++) acc[m2][j][q] = 0.f;

#pragma unroll
        for (int pass = 0; pass < 3; pass++) {
            const uint32_t aBase = smb + (pass == 2 ? SM_XLO : SM_XHI) + aoff;
            const uint32_t bBase = smb + (pass == 1 ? SM_WLO : SM_WHI) + boff;

#pragma unroll
            for (int k8 = 0; k8 < 8; k8++) {
                uint32_t afr[2][4];
                ldsm4(afr[0], aBase + k8 * 32);
                ldsm4(afr[1], aBase + 16 * XSTRIDE + k8 * 32);
#pragma unroll
                for (int jp = 0; jp < 4; jp++) {
                    uint32_t bfr[4];
                    ldsm4(bfr, bBase + jp * (16 * XSTRIDE) + k8 * 32);
                    mma16816(acc[0][2 * jp + 0], afr[0], bfr[0], bfr[1]);
                    mma16816(acc[0][2 * jp + 1], afr[0], bfr[2], bfr[3]);
                    mma16816(acc[1][2 * jp + 0], afr[1], bfr[0], bfr[1]);
                    mma16816(acc[1][2 * jp + 1], afr[1], bfr[2], bfr[3]);
                }
            }
        }

        // ---- epilogue: bias + store to g_G ----
        {
            const int g  = lane >> 2;
            const int t2 = (lane & 3) * 2;
            const float* bsm = (const float*)(sm + SM_BIAS);
#pragma unroll
            for (int m2 = 0; m2 < 2; m2++) {
                const size_t mrow = (size_t)mt * 128 + msub + m2 * 16 + g;
                float* r0 = g_G + ((size_t)dir * BT_ + mrow) * NG_;
                float* r1 = r0 + 8 * NG_;
#pragma unroll
                for (int j = 0; j < 8; j++) {
                    const int col = nsub0 + 8 * j + t2;
                    float2 bv = *(const float2*)(bsm + col);
                    *(float2*)(r0 + col) =
                        make_float2(acc[m2][j][0] + bv.x, acc[m2][j][1] + bv.y);
                    *(float2*)(r1 + col) =
                        make_float2(acc[m2][j][2] + bv.x, acc[m2][j][3] + bv.y);
                }
            }
        }
    }
}

// =======================================================================
// Kernel 2: recurrence (unchanged R6 winner). 256 CTAs, 128 thr, 2/SM.
// =======================================================================
__global__ void __launch_bounds__(128, 2) lstm_rec(
    const float* __restrict__ Whh_f, const float* __restrict__ Whh_b,
    float* __restrict__ out)
{
    __shared__ __align__(16) float h_s[2][4][64];
    __shared__ __align__(16) float2 xg_s[2][4][128];

    const int tid  = threadIdx.x;
    const int dir  = blockIdx.x >> 7;
    const int b0   = (blockIdx.x & 127) << 2;
    const int hh   = tid >> 1;
    const int type = tid & 1;

    const float* Whh = dir ? Whh_b : Whh_f;

    const int j0 = type ? (64 + hh) : hh;
    const int j1 = j0 + 128;

    unsigned long long w2a[32], w2b[32];
    {
        const ulonglong2* ra = (const ulonglong2*)(Whh + j0 * 64);
        const ulonglong2* rb = (const ulonglong2*)(Whh + j1 * 64);
#pragma unroll
        for (int i = 0; i < 16; i++) {
            ulonglong2 va = ra[i], vb = rb[i];
            w2a[2 * i] = va.x; w2a[2 * i + 1] = va.y;
            w2b[2 * i] = vb.x; w2b[2 * i + 1] = vb.y;
        }
    }

    const float s1 = type ? 0.5f : 1.0f;
    const float m1 = type ? 0.5f : 1.0f;
    const float c1 = type ? 0.5f : 0.0f;

#pragma unroll
    for (int i = 0; i < 4; i++) ((float*)h_s)[tid + i * 128] = 0.f;
    float c[4] = {0.f, 0.f, 0.f, 0.f};

    const float* xg_src = g_G + ((size_t)dir * BT_) * NG_ + (size_t)hh * 4 + type * 2;
    const uint32_t xgs_u32 = (uint32_t)__cvta_generic_to_shared(&xg_s[0][0][0]);
    float* outb = out + dir * 64 + hh;

    {
        const int t0 = dir ? (T_ - 1) : 0;
#pragma unroll
        for (int b = 0; b < 4; b++)
            cp_async8(xgs_u32 + (b * 128 + tid) * 8,
                      xg_src + ((size_t)(b0 + b) * T_ + t0) * NG_);
        cp_commit();
    }
    __syncthreads();

    for (int s = 0; s < T_; s++) {
        const int t = dir ? (T_ - 1 - s) : s;

        if (s + 1 < T_) {
            const int tn = dir ? (T_ - 2 - s) : (s + 1);
            const uint32_t dst = xgs_u32 + ((s + 1) & 1) * 4096;
#pragma unroll
            for (int b = 0; b < 4; b++)
                cp_async8(dst + (b * 128 + tid) * 8,
                          xg_src + ((size_t)(b0 + b) * T_ + tn) * NG_);
        }
        cp_commit();

        const float* cur = &h_s[s & 1][0][0];
        float* nxt = &h_s[(s & 1) ^ 1][0][0];

        unsigned long long a0[4] = {0, 0, 0, 0}, a1[4] = {0, 0, 0, 0};
#pragma unroll
        for (int q = 0; q < 16; q++) {
#pragma unroll
            for (int b = 0; b < 4; b++) {
                ulonglong2 hb = *(const ulonglong2*)(cur + b * 64 + 4 * q);
                a0[b] = ffma2(hb.x, w2a[2 * q], a0[b]);
                a0[b] = ffma2(hb.y, w2a[2 * q + 1], a0[b]);
                a1[b] = ffma2(hb.x, w2b[2 * q], a1[b]);
                a1[b] = ffma2(hb.y, w2b[2 * q + 1], a1[b]);
            }
        }

        cp_wait1();

#pragma unroll
        for (int b = 0; b < 4; b++) {
            const float2 xg = xg_s[s & 1][b][tid];
            const float g0 = red2(a0[b]) + xg.x;
            const float g1 = red2(a1[b]) + xg.y;

            const float t0  = sig_fast(g0);
            const float t1v = fmaf(tanh_fast(g1 * s1), m1, c1);

            const float v  = t0 * t1v;
            const float vr = __shfl_xor_sync(0xFFFFFFFFu, v, 1);

            c[b] = fmaf(t0, c[b], vr);
            const float h = t1v * tanh_fast(c[b]);

            if (type) {
                nxt[b * 64 + hh] = h;
                outb[((size_t)(b0 + b) * T_ + t) * 128] = h;
            }
        }
        __syncthreads();
    }
}

// =======================================================================
extern "C" void kernel_launch(void* const* d_in, const int* in_sizes, int n_in,
                              void* d_out, int out_size)
{
    const float* x    = (const float*)d_in[0];
    const float* Wihf = (const float*)d_in[1];
    const float* Whhf = (const float*)d_in[2];
    const float* bf   = (const float*)d_in[3];
    const float* Wihb = (const float*)d_in[4];
    const float* Whhb = (const float*)d_in[5];
    const float* bb   = (const float*)d_in[6];
    float* out = (float*)d_out;

    cudaFuncSetAttribute(gates_gemm, cudaFuncAttributeMaxDynamicSharedMemorySize, SM_TOTAL);

    gates_gemm<<<148, 512, SM_TOTAL>>>(x, Wihf, bf, Wihb, bb);
    lstm_rec<<<256, 128>>>(Whhf, Whhb, out);
}

// round 9
// speedup vs baseline: 2.3996x; 1.2126x over previous
#include <cuda_runtime.h>
#include <cuda_bf16.h>
#include <cstdint>

#define B_  512
#define T_  1024
#define IN_ 128
#define NG_ 256
#define BT_ (B_ * T_)
#define MTILES 4096          // BT_/128 m-tiles per dir

// xg scratch: [dir][b*T+t][hh*4 + slot], slot: 0=i,1=g,2=f,3=o  (1 GiB)
__device__ float g_G[(size_t)2 * BT_ * NG_];

// ---------------- smem map (bytes) for gates_gemm ----------------
// bf16 tiles, row stride 136 elems = 272 B (conflict-free ldmatrix)
#define XSTRIDE 272
#define SM_XHI  0
#define SM_XLO  (SM_XHI + 128 * XSTRIDE)     //  34816
#define SM_WHI  (SM_XLO + 128 * XSTRIDE)     //  69632
#define SM_WLO  (SM_WHI + 256 * XSTRIDE)     // 139264
#define SM_BIAS (SM_WLO + 256 * XSTRIDE)     // 208896
#define SM_TOTAL (SM_BIAS + 1024)            // 209920

// ---------------- ptx helpers ----------------
__device__ __forceinline__ uint32_t smem_u32(const void* p) {
    return (uint32_t)__cvta_generic_to_shared(p);
}
__device__ __forceinline__ void ldsm4(uint32_t* r, uint32_t addr) {
    asm volatile("ldmatrix.sync.aligned.m8n8.x4.shared.b16 {%0,%1,%2,%3}, [%4];"
                 : "=r"(r[0]), "=r"(r[1]), "=r"(r[2]), "=r"(r[3]) : "r"(addr));
}
__device__ __forceinline__ void mma16816(float* c, const uint32_t* a,
                                         uint32_t b0, uint32_t b1) {
    asm volatile(
        "mma.sync.aligned.m16n8k16.row.col.f32.bf16.bf16.f32 "
        "{%0,%1,%2,%3}, {%4,%5,%6,%7}, {%8,%9}, {%0,%1,%2,%3};"
        : "+f"(c[0]), "+f"(c[1]), "+f"(c[2]), "+f"(c[3])
        : "r"(a[0]), "r"(a[1]), "r"(a[2]), "r"(a[3]), "r"(b0), "r"(b1));
}

// bf16x2 pack: low half = lo arg, high half = hi arg
__device__ __forceinline__ uint32_t pack_bf16x2(float lo, float hi) {
    uint32_t r;
    asm("cvt.rn.bf16x2.f32 %0, %1, %2;" : "=r"(r) : "f"(hi), "f"(lo));
    return r;
}
// hi/lo split of two floats -> packed bf16x2 hi + residual bf16x2 lo
__device__ __forceinline__ void split2(float a, float b, uint32_t& hi, uint32_t& lo) {
    hi = pack_bf16x2(a, b);
    float ra = a - __uint_as_float(hi << 16);
    float rb = b - __uint_as_float(hi & 0xFFFF0000u);
    lo = pack_bf16x2(ra, rb);
}

// ---------------- activations (MUFU tanh) ----------------
__device__ __forceinline__ float tanh_fast(float x) {
    float y;
    asm("tanh.approx.f32 %0, %1;" : "=f"(y) : "f"(x));
    return y;
}
__device__ __forceinline__ float sig_fast(float x) {
    return fmaf(tanh_fast(0.5f * x), 0.5f, 0.5f);
}

// ---------------- f32x2 / cp.async (recurrence) ----------------
__device__ __forceinline__ unsigned long long ffma2(unsigned long long a,
                                                    unsigned long long b,
                                                    unsigned long long c) {
    unsigned long long d;
    asm("fma.rn.f32x2 %0, %1, %2, %3;" : "=l"(d) : "l"(a), "l"(b), "l"(c));
    return d;
}
__device__ __forceinline__ float red2(unsigned long long v) {
    unsigned int a, b;
    asm("mov.b64 {%0, %1}, %2;" : "=r"(a), "=r"(b) : "l"(v));
    return __uint_as_float(a) + __uint_as_float(b);
}
__device__ __forceinline__ void cp_async8(uint32_t dst, const void* src) {
    asm volatile("cp.async.ca.shared.global [%0], [%1], 8;" :: "r"(dst), "l"(src));
}
__device__ __forceinline__ void cp_commit() {
    asm volatile("cp.async.commit_group;");
}
__device__ __forceinline__ void cp_wait1() {
    asm volatile("cp.async.wait_group 1;");
}

// =======================================================================
// Kernel 1: HMMA split-precision GEMM, fused 3-term mainloop.
// D[128m,256p] = xhi*Whi + xhi*Wlo + xlo*Whi  (fp32 register accs).
// A hi/lo fragments hoisted per k8 -> 12 ldsm4 per k8 (96/tile/warp).
// 148 CTAs x 512 thr (16 warps): warp tile 32m x 64n.
// =======================================================================
__global__ void __launch_bounds__(512, 1) gates_gemm(
    const float* __restrict__ x,
    const float* __restrict__ Wf, const float* __restrict__ bf,
    const float* __restrict__ Wb, const float* __restrict__ bb)
{
    extern __shared__ char sm[];
    const uint32_t smb = smem_u32(sm);

    const int tid  = threadIdx.x;
    const int wid  = tid >> 5;
    const int lane = tid & 31;
    const int dir  = blockIdx.x & 1;
    const int cpos = blockIdx.x >> 1;   // 0..73

    const float* W    = dir ? Wb : Wf;
    const float* bias = dir ? bb : bf;

    // ---- load + split W at permuted row p (once) ----
    {
        const int j    = tid >> 1;          // 0..255
        const int half = tid & 1;           // k half: cols 0-63 / 64-127
        const int g    = j >> 6;
        const int slot = (g == 0) ? 0 : (g == 1) ? 2 : (g == 2) ? 1 : 3;
        const int p    = ((j & 63) << 2) | slot;
        const float4* wr = (const float4*)(W + j * IN_ + half * 64);
        char* whi = sm + SM_WHI + p * XSTRIDE + half * 128;
        char* wlo = sm + SM_WLO + p * XSTRIDE + half * 128;
#pragma unroll
        for (int q = 0; q < 16; q++) {
            float4 v = wr[q];
            uint32_t h0, l0, h1, l1;
            split2(v.x, v.y, h0, l0);
            split2(v.z, v.w, h1, l1);
            *(uint2*)(whi + q * 8) = make_uint2(h0, h1);
            *(uint2*)(wlo + q * 8) = make_uint2(l0, l1);
        }
        if (half == 0) ((float*)(sm + SM_BIAS))[p] = bias[j];
    }

    // warp tiling
    const int msub  = (wid & 3) * 32;
    const int nsub0 = (wid >> 2) * 64;

    // ldmatrix lane address components
    const uint32_t aoff = (uint32_t)(msub + (lane & 15)) * XSTRIDE + (lane >> 4) * 16;
    const uint32_t boff = (uint32_t)(nsub0 + (lane & 7) + ((lane >> 4) << 3)) * XSTRIDE
                          + ((lane >> 3) & 1) * 16;

    const int r0c = tid >> 5;     // conversion row base
    const int lc  = tid & 31;     // conversion col4

    for (int mt = cpos; mt < MTILES; mt += 74) {
        __syncthreads();   // x smem free (first iter: also orders W split)

        // ---- load + split x tile ----
        {
            const float* srcb = x + (size_t)mt * 128 * IN_;
#pragma unroll
            for (int i = 0; i < 4; i++) {
                const int row0 = r0c + 32 * i;
                float4 v0 = *(const float4*)(srcb + (size_t)row0 * IN_ + lc * 4);
                float4 v1 = *(const float4*)(srcb + (size_t)(row0 + 16) * IN_ + lc * 4);
                uint32_t h0, l0, h1, l1;
                split2(v0.x, v0.y, h0, l0);
                split2(v0.z, v0.w, h1, l1);
                *(uint2*)(sm + SM_XHI + row0 * XSTRIDE + lc * 8) = make_uint2(h0, h1);
                *(uint2*)(sm + SM_XLO + row0 * XSTRIDE + lc * 8) = make_uint2(l0, l1);
                split2(v1.x, v1.y, h0, l0);
                split2(v1.z, v1.w, h1, l1);
                *(uint2*)(sm + SM_XHI + (row0 + 16) * XSTRIDE + lc * 8) = make_uint2(h0, h1);
                *(uint2*)(sm + SM_XLO + (row0 + 16) * XSTRIDE + lc * 8) = make_uint2(l0, l1);
            }
        }
        __syncthreads();

        // ---- fused 3-term mma accumulate ----
        float acc[2][8][4];
#pragma unroll
        for (int m2 = 0; m2 < 2; m2++)
#pragma unroll
            for (int j = 0; j < 8; j++)
#pragma unroll
                for (int q = 0; q < 4; q++) acc[m2][j][q] = 0.f;

        const uint32_t aHi = smb + SM_XHI + aoff;
        const uint32_t aLo = smb + SM_XLO + aoff;
        const uint32_t bHi = smb + SM_WHI + boff;
        const uint32_t bLo = smb + SM_WLO + boff;

#pragma unroll
        for (int k8 = 0; k8 < 8; k8++) {
            uint32_t ah0[4], ah1[4], al0[4], al1[4];
            ldsm4(ah0, aHi + k8 * 32);
            ldsm4(ah1, aHi + 16 * XSTRIDE + k8 * 32);
            ldsm4(al0, aLo + k8 * 32);
            ldsm4(al1, aLo + 16 * XSTRIDE + k8 * 32);
#pragma unroll
            for (int jp = 0; jp < 4; jp++) {
                uint32_t bh[4], bl[4];
                ldsm4(bh, bHi + jp * (16 * XSTRIDE) + k8 * 32);
                ldsm4(bl, bLo + jp * (16 * XSTRIDE) + k8 * 32);
                // xhi * Whi
                mma16816(acc[0][2 * jp + 0], ah0, bh[0], bh[1]);
                mma16816(acc[0][2 * jp + 1], ah0, bh[2], bh[3]);
                mma16816(acc[1][2 * jp + 0], ah1, bh[0], bh[1]);
                mma16816(acc[1][2 * jp + 1], ah1, bh[2], bh[3]);
                // xhi * Wlo
                mma16816(acc[0][2 * jp + 0], ah0, bl[0], bl[1]);
                mma16816(acc[0][2 * jp + 1], ah0, bl[2], bl[3]);
                mma16816(acc[1][2 * jp + 0], ah1, bl[0], bl[1]);
                mma16816(acc[1][2 * jp + 1], ah1, bl[2], bl[3]);
                // xlo * Whi
                mma16816(acc[0][2 * jp + 0], al0, bh[0], bh[1]);
                mma16816(acc[0][2 * jp + 1], al0, bh[2], bh[3]);
                mma16816(acc[1][2 * jp + 0], al1, bh[0], bh[1]);
                mma16816(acc[1][2 * jp + 1], al1, bh[2], bh[3]);
            }
        }

        // ---- epilogue: bias + store to g_G ----
        {
            const int g  = lane >> 2;
            const int t2 = (lane & 3) * 2;
            const float* bsm = (const float*)(sm + SM_BIAS);
#pragma unroll
            for (int m2 = 0; m2 < 2; m2++) {
                const size_t mrow = (size_t)mt * 128 + msub + m2 * 16 + g;
                float* r0 = g_G + ((size_t)dir * BT_ + mrow) * NG_;
                float* r1 = r0 + 8 * NG_;
#pragma unroll
                for (int j = 0; j < 8; j++) {
                    const int col = nsub0 + 8 * j + t2;
                    float2 bv = *(const float2*)(bsm + col);
                    *(float2*)(r0 + col) =
                        make_float2(acc[m2][j][0] + bv.x, acc[m2][j][1] + bv.y);
                    *(float2*)(r1 + col) =
                        make_float2(acc[m2][j][2] + bv.x, acc[m2][j][3] + bv.y);
                }
            }
        }
    }
}

// =======================================================================
// Kernel 2: recurrence (R6 winner) + CTA de-phasing.
// Odd CTAs burn ~1200 cyc of dependent FFMA before the loop so the two
// co-resident CTAs' epilogue bubbles interleave with matvec FFMA2.
// =======================================================================
__global__ void __launch_bounds__(128, 2) lstm_rec(
    const float* __restrict__ Whh_f, const float* __restrict__ Whh_b,
    float* __restrict__ out)
{
    __shared__ __align__(16) float h_s[2][4][64];
    __shared__ __align__(16) float2 xg_s[2][4][128];

    const int tid  = threadIdx.x;
    const int dir  = blockIdx.x >> 7;
    const int b0   = (blockIdx.x & 127) << 2;
    const int hh   = tid >> 1;
    const int type = tid & 1;

    // de-phase: odd CTAs delay ~1200 cyc (300 dependent FFMA)
    if (blockIdx.x & 1) {
        float v = (float)tid;
#pragma unroll 1
        for (int i = 0; i < 300; i++)
            asm volatile("fma.rn.f32 %0, %0, %1, %2;"
                         : "+f"(v) : "f"(1.0000001f), "f"(1e-7f));
        asm volatile("" :: "f"(v));
    }

    const float* Whh = dir ? Whh_b : Whh_f;

    const int j0 = type ? (64 + hh) : hh;
    const int j1 = j0 + 128;

    unsigned long long w2a[32], w2b[32];
    {
        const ulonglong2* ra = (const ulonglong2*)(Whh + j0 * 64);
        const ulonglong2* rb = (const ulonglong2*)(Whh + j1 * 64);
#pragma unroll
        for (int i = 0; i < 16; i++) {
            ulonglong2 va = ra[i], vb = rb[i];
            w2a[2 * i] = va.x; w2a[2 * i + 1] = va.y;
            w2b[2 * i] = vb.x; w2b[2 * i + 1] = vb.y;
        }
    }

    const float s1 = type ? 0.5f : 1.0f;
    const float m1 = type ? 0.5f : 1.0f;
    const float c1 = type ? 0.5f : 0.0f;

#pragma unroll
    for (int i = 0; i < 4; i++) ((float*)h_s)[tid + i * 128] = 0.f;
    float c[4] = {0.f, 0.f, 0.f, 0.f};

    const float* xg_src = g_G + ((size_t)dir * BT_) * NG_ + (size_t)hh * 4 + type * 2;
    const uint32_t xgs_u32 = (uint32_t)__cvta_generic_to_shared(&xg_s[0][0][0]);
    float* outb = out + dir * 64 + hh;

    {
        const int t0 = dir ? (T_ - 1) : 0;
#pragma unroll
        for (int b = 0; b < 4; b++)
            cp_async8(xgs_u32 + (b * 128 + tid) * 8,
                      xg_src + ((size_t)(b0 + b) * T_ + t0) * NG_);
        cp_commit();
    }
    __syncthreads();

    for (int s = 0; s < T_; s++) {
        const int t = dir ? (T_ - 1 - s) : s;

        if (s + 1 < T_) {
            const int tn = dir ? (T_ - 2 - s) : (s + 1);
            const uint32_t dst = xgs_u32 + ((s + 1) & 1) * 4096;
#pragma unroll
            for (int b = 0; b < 4; b++)
                cp_async8(dst + (b * 128 + tid) * 8,
                          xg_src + ((size_t)(b0 + b) * T_ + tn) * NG_);
        }
        cp_commit();

        const float* cur = &h_s[s & 1][0][0];
        float* nxt = &h_s[(s & 1) ^ 1][0][0];

        unsigned long long a0[4] = {0, 0, 0, 0}, a1[4] = {0, 0, 0, 0};
#pragma unroll
        for (int q = 0; q < 16; q++) {
#pragma unroll
            for (int b = 0; b < 4; b++) {
                ulonglong2 hb = *(const ulonglong2*)(cur + b * 64 + 4 * q);
                a0[b] = ffma2(hb.x, w2a[2 * q], a0[b]);
                a0[b] = ffma2(hb.y, w2a[2 * q + 1], a0[b]);
                a1[b] = ffma2(hb.x, w2b[2 * q], a1[b]);
                a1[b] = ffma2(hb.y, w2b[2 * q + 1], a1[b]);
            }
        }

        cp_wait1();

#pragma unroll
        for (int b = 0; b < 4; b++) {
            const float2 xg = xg_s[s & 1][b][tid];
            const float g0 = red2(a0[b]) + xg.x;
            const float g1 = red2(a1[b]) + xg.y;

            const float t0  = sig_fast(g0);
            const float t1v = fmaf(tanh_fast(g1 * s1), m1, c1);

            const float v  = t0 * t1v;
            const float vr = __shfl_xor_sync(0xFFFFFFFFu, v, 1);

            c[b] = fmaf(t0, c[b], vr);
            const float h = t1v * tanh_fast(c[b]);

            if (type) {
                nxt[b * 64 + hh] = h;
                outb[((size_t)(b0 + b) * T_ + t) * 128] = h;
            }
        }
        __syncthreads();
    }
}

// =======================================================================
extern "C" void kernel_launch(void* const* d_in, const int* in_sizes, int n_in,
                              void* d_out, int out_size)
{
    const float* x    = (const float*)d_in[0];
    const float* Wihf = (const float*)d_in[1];
    const float* Whhf = (const float*)d_in[2];
    const float* bf   = (const float*)d_in[3];
    const float* Wihb = (const float*)d_in[4];
    const float* Whhb = (const float*)d_in[5];
    const float* bb   = (const float*)d_in[6];
    float* out = (float*)d_out;

    cudaFuncSetAttribute(gates_gemm, cudaFuncAttributeMaxDynamicSharedMemorySize, SM_TOTAL);

    gates_gemm<<<148, 512, SM_TOTAL>>>(x, Wihf, bf, Wihb, bb);
    lstm_rec<<<256, 128>>>(Whhf, Whhb, out);
}